// round 6
// baseline (speedup 1.0000x reference)
#include <cuda_runtime.h>
#include <math.h>

#define B_ 2
#define L_ 512
#define C_ 256
#define H_ 8
#define D_ 32
#define SCALE_ 0.17677669529663687f   // 1/sqrt(32)

typedef unsigned long long ull;

// ---------------- f32x2 packed-FMA helpers (sm_103a) ------------------------
__device__ __forceinline__ ull pack2(float a, float b) {
    ull r; asm("mov.b64 %0, {%1, %2};" : "=l"(r) : "f"(a), "f"(b)); return r;
}
__device__ __forceinline__ void unpack2(ull v, float& a, float& b) {
    asm("mov.b64 {%0, %1}, %2;" : "=f"(a), "=f"(b) : "l"(v));
}
__device__ __forceinline__ void ffma2(ull& d, ull a, ull b) {
    asm("fma.rn.f32x2 %0, %1, %2, %0;" : "+l"(d) : "l"(a), "l"(b));
}
__device__ __forceinline__ void cp16(float* smem_dst, const float* gsrc) {
    unsigned s = (unsigned)__cvta_generic_to_shared(smem_dst);
    asm volatile("cp.async.cg.shared.global [%0], [%1], 16;" :: "r"(s), "l"(gsrc) : "memory");
}
__device__ __forceinline__ void cp_commit() {
    asm volatile("cp.async.commit_group;" ::: "memory");
}

// ------------------------- scratch (device globals) -------------------------
__device__ float g_q[B_*H_*L_*D_];          // 1 MB  [b][h][l][d]
__device__ float g_k[B_*H_*L_*D_];          // 1 MB
__device__ float g_v[B_*H_*L_*D_];          // 1 MB
__device__ float g_qk[B_*L_*H_*L_];         // 16 MB [b][l][h][m]
__device__ float g_p [B_*L_*H_*L_];         // 16 MB [b][l][h][m]
__device__ float g_att[B_*L_*C_];           // 1 MB  [b][l][h*32+d]

// ===========================================================================
// K1/K5 GEMM: out[m][n] = sum_k A[m][k]*W[n][k]; 64x32 tile, 128 thr.
// ===========================================================================
__global__ __launch_bounds__(128) void gemm_kernel(
    const float* __restrict__ A, const float* __restrict__ W,
    const float* __restrict__ bias, float* __restrict__ out, int mode)
{
    __shared__ __align__(16) float As[32][68];
    __shared__ __align__(16) float Ws[32][36];
    const float* Ap = (mode == 0) ? A : g_att;
    int tid  = threadIdx.x;
    int row0 = blockIdx.x * 64;
    int col0 = blockIdx.y * 32;
    int tx = tid & 7, ty = tid >> 3;

    ull acc2[2][4];
    #pragma unroll
    for (int i = 0; i < 2; i++)
        #pragma unroll
        for (int j = 0; j < 4; j++) acc2[i][j] = 0ull;

    for (int kc = 0; kc < 256; kc += 32) {
        #pragma unroll
        for (int i = 0; i < 4; i++) {
            int idx = tid + i * 128;
            int r = idx >> 3, c4 = idx & 7;
            float4 av = *(const float4*)&Ap[(size_t)(row0 + r) * 256 + kc + c4 * 4];
            As[c4*4+0][r] = av.x; As[c4*4+1][r] = av.y;
            As[c4*4+2][r] = av.z; As[c4*4+3][r] = av.w;
        }
        #pragma unroll
        for (int i = 0; i < 2; i++) {
            int idx = tid + i * 128;
            int r = idx >> 3, c4 = idx & 7;
            float4 wv = *(const float4*)&W[(size_t)(col0 + r) * 256 + kc + c4 * 4];
            Ws[c4*4+0][r] = wv.x; Ws[c4*4+1][r] = wv.y;
            Ws[c4*4+2][r] = wv.z; Ws[c4*4+3][r] = wv.w;
        }
        __syncthreads();
        #pragma unroll
        for (int kk = 0; kk < 32; kk++) {
            ulonglong2 a2 = *(const ulonglong2*)&As[kk][ty * 4];
            float4 b4 = *(const float4*)&Ws[kk][tx * 4];
            ull bd[4] = { pack2(b4.x, b4.x), pack2(b4.y, b4.y),
                          pack2(b4.z, b4.z), pack2(b4.w, b4.w) };
            #pragma unroll
            for (int j = 0; j < 4; j++) {
                ffma2(acc2[0][j], a2.x, bd[j]);
                ffma2(acc2[1][j], a2.y, bd[j]);
            }
        }
        __syncthreads();
    }

    #pragma unroll
    for (int i2 = 0; i2 < 2; i2++) {
        #pragma unroll
        for (int j = 0; j < 4; j++) {
            float v0, v1;
            unpack2(acc2[i2][j], v0, v1);
            int n = col0 + tx * 4 + j;
            #pragma unroll
            for (int half = 0; half < 2; half++) {
                int m  = row0 + ty * 4 + i2 * 2 + half;
                float val = half ? v1 : v0;
                int bb = m >> 9, l = m & 511;
                if (mode == 0) {
                    int s = n >> 8, rem = n & 255, h = rem >> 5, d = rem & 31;
                    float* dst = (s == 0) ? g_q : (s == 1) ? g_k : g_v;
                    dst[(((size_t)bb * H_ + h) * L_ + l) * D_ + d] = val;
                } else {
                    out[(size_t)m * 256 + n] = val + bias[n];
                }
            }
        }
    }
}

// ===========================================================================
// K2: qk[b,l,h,m] = q.k  — block=(lt32, bh, mhalf); k half staged (36.9KB)
// ===========================================================================
__global__ __launch_bounds__(256) void qk_kernel()
{
    extern __shared__ __align__(16) float smqk[];
    float* ks = smqk;              // [256][36]
    float* qs = smqk + 256 * 36;   // [32][32]
    int tid = threadIdx.x;
    int bh = blockIdx.y, lt = blockIdx.x, mh = blockIdx.z;
    int b = bh >> 3, h = bh & 7;

    const float* kb = g_k + (size_t)bh * (512 * 32) + (size_t)mh * 256 * 32;
    const float* qb = g_q + (size_t)bh * (512 * 32) + (size_t)lt * 32 * 32;

    #pragma unroll
    for (int i = 0; i < 8; i++) {
        int idx = tid + i * 256;
        int r = idx >> 3, c4 = idx & 7;
        *(float4*)&ks[r * 36 + c4 * 4] = *(const float4*)&kb[(size_t)idx * 4];
    }
    { int r = tid >> 3, c4 = tid & 7;
      *(float4*)&qs[r * 32 + c4 * 4] = *(const float4*)&qb[(size_t)tid * 4]; }
    __syncthreads();

    int l = tid >> 3, mg = tid & 7;
    ull q2[16];
    #pragma unroll
    for (int j = 0; j < 8; j++) {
        ulonglong2 t = *(const ulonglong2*)&qs[l * 32 + j * 4];
        q2[2*j] = t.x; q2[2*j+1] = t.y;
    }
    float* outp = g_qk + (((size_t)b * 512 + lt * 32 + l) * 8 + h) * 512 + mh * 256;
    #pragma unroll 4
    for (int i = 0; i < 32; i++) {
        int m = mg + i * 8;
        ull sa = 0ull, sb = 0ull;
        #pragma unroll
        for (int j = 0; j < 8; j++) {
            ulonglong2 kv = *(const ulonglong2*)&ks[m * 36 + j * 4];
            ffma2(sa, q2[2*j], kv.x);
            ffma2(sb, q2[2*j+1], kv.y);
        }
        float a0, a1, b0, b1;
        unpack2(sa, a0, a1); unpack2(sb, b0, b1);
        outp[m] = (a0 + a1) + (b0 + b1);
    }
}

// ===========================================================================
// K3: HBM-bound hot kernel with cp.async double-buffered rp stream.
// block=(b,l); 16 chunks of 16 c; buffers 512x20 (conflict-free).
// ===========================================================================
#define RELBUF (512 * 20)
#define REL_SMEM_FLOATS (2 * RELBUF + 2048 + 8 * 512 + 40)

__global__ __launch_bounds__(256) void rel_kernel(
    const float* __restrict__ rp, const float* __restrict__ w_rel,
    const float* __restrict__ b_rel, const float* __restrict__ ln_g,
    const float* __restrict__ ln_b)
{
    extern __shared__ __align__(16) float smr[];
    float* buf0 = smr;                        // [512][20]
    float* buf1 = smr + RELBUF;               // [512][20]
    float* wp   = smr + 2 * RELBUF;           // 2048 weight pairs
    float* lg   = wp + 2048;                  // [8][512]
    float* par  = lg + 8 * 512;               // 24
    float* inv_s= par + 32;                   // 8

    int tid = threadIdx.x;
    int bid = blockIdx.x;                     // b*512 + l

    #pragma unroll
    for (int i = 0; i < 8; i++) {
        int idx = tid + i * 256;
        int e = idx & 3, h2 = (idx >> 2) & 3, c2 = idx >> 4;
        int h = 2 * h2 + (e >> 1), c = 2 * c2 + (e & 1);
        wp[idx] = w_rel[h * 256 + c];
    }
    if (tid < 8) { par[tid] = b_rel[tid]; par[8+tid] = ln_g[tid]; par[16+tid] = ln_b[tid]; }

    const float* rpb = rp + (size_t)bid * (512 * 256);
    int m0 = tid, m1 = tid + 256;

    ull raA[8], raB[8];
    #pragma unroll
    for (int h = 0; h < 8; h++) { raA[h] = 0ull; raB[h] = 0ull; }

    // prologue: stage chunk 0 into buf0
    #pragma unroll
    for (int i = 0; i < 8; i++) {
        int idx = tid + i * 256;
        int r = idx >> 2, c4 = idx & 3;
        cp16(&buf0[r * 20 + c4 * 4], &rpb[(size_t)r * 256 + c4 * 4]);
    }
    cp_commit();

    for (int ch = 0; ch < 16; ch++) {
        float* cur = (ch & 1) ? buf1 : buf0;
        float* nxt = (ch & 1) ? buf0 : buf1;
        __syncthreads();                       // prev compute done (nxt reads finished)
        if (ch + 1 < 16) {
            #pragma unroll
            for (int i = 0; i < 8; i++) {
                int idx = tid + i * 256;
                int r = idx >> 2, c4 = idx & 3;
                cp16(&nxt[r * 20 + c4 * 4],
                     &rpb[(size_t)r * 256 + (ch + 1) * 16 + c4 * 4]);
            }
            cp_commit();
            asm volatile("cp.async.wait_group 1;" ::: "memory");
        } else {
            asm volatile("cp.async.wait_group 0;" ::: "memory");
        }
        __syncthreads();                       // cur visible to all

        const float* t0 = &cur[m0 * 20];
        const float* t1 = &cur[m1 * 20];
        #pragma unroll
        for (int c4 = 0; c4 < 4; c4++) {
            ulonglong2 r0 = *(const ulonglong2*)&t0[c4 * 4];
            ulonglong2 r1 = *(const ulonglong2*)&t1[c4 * 4];
            int g2 = ch * 8 + c4 * 2;
            #pragma unroll
            for (int h2 = 0; h2 < 4; h2++) {
                ulonglong2 wA = *(const ulonglong2*)&wp[(g2 * 4 + h2) * 4];
                ulonglong2 wB = *(const ulonglong2*)&wp[((g2 + 1) * 4 + h2) * 4];
                ffma2(raA[2*h2],   r0.x, wA.x); ffma2(raA[2*h2+1], r0.x, wA.y);
                ffma2(raA[2*h2],   r0.y, wB.x); ffma2(raA[2*h2+1], r0.y, wB.y);
                ffma2(raB[2*h2],   r1.x, wA.x); ffma2(raB[2*h2+1], r1.x, wA.y);
                ffma2(raB[2*h2],   r1.y, wB.x); ffma2(raB[2*h2+1], r1.y, wB.y);
            }
        }
    }

    // bias + exact GELU + LayerNorm over h, per row
    float relA[8], relB[8];
    {
        float muA = 0.f, muB = 0.f;
        #pragma unroll
        for (int h = 0; h < 8; h++) {
            float lo, hi;
            unpack2(raA[h], lo, hi);
            float xv = lo + hi + par[h];
            relA[h] = 0.5f * xv * (1.f + erff(xv * 0.7071067811865475f));
            muA += relA[h];
            unpack2(raB[h], lo, hi);
            xv = lo + hi + par[h];
            relB[h] = 0.5f * xv * (1.f + erff(xv * 0.7071067811865475f));
            muB += relB[h];
        }
        muA *= 0.125f; muB *= 0.125f;
        float vA = 0.f, vB = 0.f;
        #pragma unroll
        for (int h = 0; h < 8; h++) {
            float dA = relA[h] - muA; vA += dA * dA;
            float dB = relB[h] - muB; vB += dB * dB;
        }
        float rA = rsqrtf(vA * 0.125f + 1e-5f), rB = rsqrtf(vB * 0.125f + 1e-5f);
        #pragma unroll
        for (int h = 0; h < 8; h++) {
            relA[h] = (relA[h] - muA) * rA * par[8+h] + par[16+h];
            relB[h] = (relB[h] - muB) * rB * par[8+h] + par[16+h];
        }
    }

    // add q.k logits, scale, into smem
    const float* qkb = g_qk + (size_t)bid * 4096;
    #pragma unroll
    for (int h = 0; h < 8; h++) {
        lg[h * 512 + m0] = (qkb[h * 512 + m0] + relA[h]) * SCALE_;
        lg[h * 512 + m1] = (qkb[h * 512 + m1] + relB[h]) * SCALE_;
    }
    __syncthreads();

    // softmax: warp per h
    {
        int lane = tid & 31, h = tid >> 5;
        float* row = &lg[h * 512];
        float vals[16];
        float mx = -1e30f;
        #pragma unroll
        for (int j = 0; j < 16; j++) { vals[j] = row[lane + 32 * j]; mx = fmaxf(mx, vals[j]); }
        #pragma unroll
        for (int o = 16; o > 0; o >>= 1) mx = fmaxf(mx, __shfl_xor_sync(0xffffffff, mx, o));
        float sum = 0.f;
        #pragma unroll
        for (int j = 0; j < 16; j++) {
            float e = __expf(vals[j] - mx);
            row[lane + 32 * j] = e;
            sum += e;
        }
        #pragma unroll
        for (int o = 16; o > 0; o >>= 1) sum += __shfl_xor_sync(0xffffffff, sum, o);
        if (lane == 0) inv_s[h] = 1.f / sum;
    }
    __syncthreads();

    // write normalized probs (coalesced float4)
    float* pb = g_p + (size_t)bid * 4096;
    #pragma unroll
    for (int i = 0; i < 4; i++) {
        int idx4 = tid + i * 256;
        int h = idx4 >> 7;
        float4 v = *(const float4*)&lg[h * 512 + (idx4 & 127) * 4];
        float inv = inv_s[h];
        v.x *= inv; v.y *= inv; v.z *= inv; v.w *= inv;
        *(float4*)&pb[(size_t)idx4 * 4] = v;
    }
}

// ===========================================================================
// K4: PV — block=(lt16, bh); thread=(mhalf, l, dquad); one smem reduce.
// ===========================================================================
#define PV_SMEM_FLOATS (512 * 36 + 256 * 4)

__global__ __launch_bounds__(256) void pv_kernel()
{
    extern __shared__ __align__(16) float smpv[];
    float* vs = smpv;                        // [512][36]
    float* pp = smpv + 512 * 36;             // [256][4]
    int tid = threadIdx.x;
    int bh = blockIdx.y, lt = blockIdx.x;
    int b = bh >> 3, h = bh & 7;

    const float* vb = g_v + (size_t)bh * (512 * 32);
    #pragma unroll
    for (int i = 0; i < 16; i++) {
        int idx = tid + i * 256;
        int r = idx >> 3, c4 = idx & 7;
        *(float4*)&vs[r * 36 + c4 * 4] = *(const float4*)&vb[(size_t)idx * 4];
    }
    __syncthreads();

    int dq = tid & 7, l = (tid >> 3) & 15, mh = tid >> 7;
    const float* prow = g_p + (((size_t)b * 512 + lt * 16 + l) * 8 + h) * 512 + mh * 256;
    const float* vsh  = &vs[mh * 256 * 36];
    ull a0 = 0ull, a1 = 0ull;
    #pragma unroll 4
    for (int m4 = 0; m4 < 256; m4 += 4) {
        float4 p4 = *(const float4*)&prow[m4];
        float pv[4] = {p4.x, p4.y, p4.z, p4.w};
        #pragma unroll
        for (int s = 0; s < 4; s++) {
            ull pd = pack2(pv[s], pv[s]);
            ulonglong2 v2 = *(const ulonglong2*)&vsh[(m4 + s) * 36 + dq * 4];
            ffma2(a0, pd, v2.x);
            ffma2(a1, pd, v2.y);
        }
    }
    float o0, o1, o2, o3;
    unpack2(a0, o0, o1); unpack2(a1, o2, o3);
    *(float4*)&pp[tid * 4] = make_float4(o0, o1, o2, o3);
    __syncthreads();
    if (tid < 128) {
        float4 t0 = *(const float4*)&pp[tid * 4];
        float4 t1 = *(const float4*)&pp[(tid + 128) * 4];
        float4 o = make_float4(t0.x + t1.x, t0.y + t1.y, t0.z + t1.z, t0.w + t1.w);
        *(float4*)&g_att[((size_t)b * 512 + lt * 16 + l) * 256 + h * 32 + dq * 4] = o;
    }
}

// ===========================================================================
extern "C" void kernel_launch(void* const* d_in, const int* in_sizes, int n_in,
                              void* d_out, int out_size)
{
    const float* x      = (const float*)d_in[0];
    const float* rp     = (const float*)d_in[1];
    const float* w_qkv  = (const float*)d_in[2];
    const float* w_rel  = (const float*)d_in[3];
    const float* b_rel  = (const float*)d_in[4];
    const float* ln_g   = (const float*)d_in[5];
    const float* ln_b   = (const float*)d_in[6];
    const float* w_proj = (const float*)d_in[7];
    const float* b_proj = (const float*)d_in[8];
    float* out = (float*)d_out;

    int qk_smem  = (256 * 36 + 32 * 32) * (int)sizeof(float);
    int rel_smem = REL_SMEM_FLOATS * (int)sizeof(float);
    int pv_smem  = PV_SMEM_FLOATS * (int)sizeof(float);
    cudaFuncSetAttribute(qk_kernel,  cudaFuncAttributeMaxDynamicSharedMemorySize, qk_smem);
    cudaFuncSetAttribute(rel_kernel, cudaFuncAttributeMaxDynamicSharedMemorySize, rel_smem);
    cudaFuncSetAttribute(pv_kernel,  cudaFuncAttributeMaxDynamicSharedMemorySize, pv_smem);

    // K1: qkv projection
    gemm_kernel<<<dim3(16, 24), 128>>>(x, w_qkv, nullptr, nullptr, 0);
    // K2: qk logits (grid 512)
    qk_kernel<<<dim3(16, 16, 2), 256, qk_smem>>>();
    // K3: rel bias + softmax (HBM-bound, cp.async pipelined)
    rel_kernel<<<1024, 256, rel_smem>>>(rp, w_rel, b_rel, ln_g, ln_b);
    // K4: PV (grid 512)
    pv_kernel<<<dim3(32, 16), 256, pv_smem>>>();
    // K5: output projection + bias
    gemm_kernel<<<dim3(16, 8), 128>>>(nullptr, w_proj, b_proj, out, 1);
}